// round 15
// baseline (speedup 1.0000x reference)
#include <cuda_runtime.h>
#include <cuda_fp16.h>

// Problem constants
#define KSZ   15
#define PAD   10
#define L1    134
#define MQ    17956          // L1*L1 queries
#define NMEM  16384
#define KDIM  225
#define NC    67             // per-axis queries per parity class
#define MC    4489           // queries per class
#define KC    64             // compressed K (8x8 source window)
#define NCH   64             // j-chunks of 256
#define BPC   36             // M-tiles (of 128) per class
#define GEMM_BLOCKS 144      // 4 classes * 36
#define GEMM_THREADS 256
#define TILE_B 16384         // bytes per (A tile, split): 128 rows x 128B
#define CHUNK_B 32768        // bytes per (B chunk, split): 256 rows x 128B
// smem layout: A (32KB) | 2 bufs x (2 splits x 32KB + 1KB norms)
#define SM_A   0
#define SM_B   32768
#define BUFST  66560
#define GEMM_SMEM (32768 + 2*BUFST)   // 165888

// -------- device scratch -----------------------------------------------------
__device__ __align__(16) unsigned char g_Ah[4 * BPC * 2 * TILE_B]; // fp16 A splits
__device__ __align__(16) unsigned char g_Bh[4 * NCH * 2 * CHUNK_B];// fp16 B splits
__device__ __align__(16) float g_m2f[4 * NMEM * KC];  // fp32 compressed mem
__device__ __align__(16) float g_nhn[NMEM];           // NEGATED half norms -0.5|m|^2
__device__ __align__(16) int4 g_cand4[MQ];            // top-2 per j-half (xy/zw)
__device__ int   g_idx[MQ];
__device__ float g_raw[64 * 64];

// -------- helpers ------------------------------------------------------------
__device__ __forceinline__ void split2h(float v, unsigned short& h0,
                                        unsigned short& h1) {
    __half a = __float2half_rn(v);
    float r = v - __half2float(a);
    __half b = __float2half_rn(r);
    h0 = __half_as_ushort(a);
    h1 = __half_as_ushort(b);
}

// fp32-accumulate MMA (main product)
__device__ __forceinline__ void mma16816(float& d0, float& d1, float& d2, float& d3,
                                         unsigned a0, unsigned a1, unsigned a2,
                                         unsigned a3, unsigned b0, unsigned b1) {
    asm volatile(
        "mma.sync.aligned.m16n8k16.row.col.f32.f16.f16.f32 "
        "{%0,%1,%2,%3},{%4,%5,%6,%7},{%8,%9},{%0,%1,%2,%3};"
        : "+f"(d0), "+f"(d1), "+f"(d2), "+f"(d3)
        : "r"(a0), "r"(a1), "r"(a2), "r"(a3), "r"(b0), "r"(b1));
}

// fp16-accumulate MMA (small cross products; 2x issue rate expected)
__device__ __forceinline__ void mma16816h(unsigned& d0, unsigned& d1,
                                          unsigned a0, unsigned a1, unsigned a2,
                                          unsigned a3, unsigned b0, unsigned b1) {
    asm volatile(
        "mma.sync.aligned.m16n8k16.row.col.f16.f16.f16.f16 "
        "{%0,%1},{%2,%3,%4,%5},{%6,%7},{%0,%1};"
        : "+r"(d0), "+r"(d1)
        : "r"(a0), "r"(a1), "r"(a2), "r"(a3), "r"(b0), "r"(b1));
}

__device__ __forceinline__ void cpa16(unsigned dst, const void* src) {
    asm volatile("cp.async.cg.shared.global [%0], [%1], 16;" :: "r"(dst), "l"(src));
}
__device__ __forceinline__ void cpa_commit() {
    asm volatile("cp.async.commit_group;" ::: "memory");
}
__device__ __forceinline__ void cpa_wait0() {
    asm volatile("cp.async.wait_group 0;" ::: "memory");
}

// rank-before: larger score first; ties -> lower index
__device__ __forceinline__ bool rank_gt(float a, int ia, float b, int ib) {
    return (a > b) || (a == b && ia < ib);
}

// ---------------------------------------------------------------------------
// slot sum (validated in R4)
// ---------------------------------------------------------------------------
__device__ __forceinline__ float slotsum(const float* __restrict__ row,
                                         int py, int px, int sy, int sx) {
    int i0 = py ? 2 * sy - 1 : 2 * sy;
    int i1 = i0 + 1;
    int j0 = px ? 2 * sx - 1 : 2 * sx;
    int j1 = j0 + 1;
    float s = 0.f;
    if ((unsigned)i0 < 15u) {
        if ((unsigned)j0 < 15u) s += row[i0 * KSZ + j0];
        if ((unsigned)j1 < 15u) s += row[i0 * KSZ + j1];
    }
    if ((unsigned)i1 < 15u) {
        if ((unsigned)j0 < 15u) s += row[i1 * KSZ + j0];
        if ((unsigned)j1 < 15u) s += row[i1 * KSZ + j1];
    }
    return s;
}

// chunk-permuted in-row byte offset for logical k (0..63)
__device__ __forceinline__ int kpos(int row, int k) {
    int c = (k >> 1) & 3, h = (k >> 3) & 1, kk = k >> 4;
    int chunk = ((c * 2 + h + row) & 7);
    return chunk * 16 + kk * 4 + (k & 1) * 2;
}

// ---------------------------------------------------------------------------
// Prep B: compressed mem -> 2 fp16 splits in chunk-permuted 256-row chunks
// ---------------------------------------------------------------------------
__global__ void prep_Bh(const float* __restrict__ mem) {
    int e = blockIdx.x * 256 + threadIdx.x;
    if (e >= 4 * NMEM * 32) return;
    int k2  = e & 31;
    int j   = (e >> 5) & (NMEM - 1);
    int cls = e >> 19;
    int py = cls >> 1, px = cls & 1;
    int s0 = 2 * k2, sy = s0 >> 3, sx = s0 & 7;
    const float* row = mem + j * KDIM;
    float vx = slotsum(row, py, px, sy, sx);
    float vy = slotsum(row, py, px, sy, sx + 1);

    *(float2*)&g_m2f[((size_t)(cls * NMEM + j) << 6) + s0] = make_float2(vx, vy);

    unsigned short x0, x1, y0, y1;
    split2h(vx, x0, x1);
    split2h(vy, y0, y1);
    int r = j & 255;
    int off = kpos(r, s0);
    size_t base = ((size_t)(cls * NCH + (j >> 8)) * 2) * CHUNK_B + (size_t)r * 128;
    ushort2 v0; v0.x = x0; v0.y = y0;
    ushort2 v1; v1.x = x1; v1.y = y1;
    *(ushort2*)(g_Bh + base + off) = v0;
    *(ushort2*)(g_Bh + base + CHUNK_B + off) = v1;
}

// ---------------------------------------------------------------------------
// Prep A: compressed queries -> 2 fp16 splits in chunk-permuted tiles
// ---------------------------------------------------------------------------
__global__ void prep_Ah(const float* __restrict__ image) {
    int e = blockIdx.x * 256 + threadIdx.x;
    if (e >= 4 * BPC * 128 * 32) return;
    int k2  = e & 31;
    int r   = (e >> 5) & 127;
    int r1  = e >> 12;                  // cls*BPC + tile
    int tile = r1 % BPC;
    int cls  = r1 / BPC;
    int py = cls >> 1, px = cls & 1;
    float vx = 0.f, vy = 0.f;
    int qc = tile * 128 + r;
    int s0 = 2 * k2, sy = s0 >> 3, sx = s0 & 7;
    if (qc < MC) {
        int a = qc / NC, b = qc - a * NC;
        int by = ((py + 2 * a) - PAD) >> 1;
        int bx = ((px + 2 * b) - PAD) >> 1;
        int yy = by + sy;
        if ((unsigned)yy < 64u) {
            int x0i = bx + sx, x1i = x0i + 1;
            if ((unsigned)x0i < 64u) vx = image[yy * 64 + x0i];
            if ((unsigned)x1i < 64u) vy = image[yy * 64 + x1i];
        }
    }
    unsigned short x0, x1, y0, y1;
    split2h(vx, x0, x1);
    split2h(vy, y0, y1);
    int off = kpos(r, s0);
    size_t base = (size_t)(r1 * 2) * TILE_B + (size_t)r * 128;
    ushort2 v0; v0.x = x0; v0.y = y0;
    ushort2 v1; v1.x = x1; v1.y = y1;
    *(ushort2*)(g_Ah + base + off) = v0;
    *(ushort2*)(g_Ah + base + TILE_B + off) = v1;
}

// Prep: NEGATED half squared norms (-0.5*|m|^2), one warp per row
__global__ void prep_norms(const float* __restrict__ mem) {
    int gw   = (blockIdx.x * blockDim.x + threadIdx.x) >> 5;
    int lane = threadIdx.x & 31;
    if (gw >= NMEM) return;
    const float* row = mem + gw * KDIM;
    float s = 0.f;
    for (int k = lane; k < KDIM; k += 32) { float v = row[k]; s += v * v; }
    #pragma unroll
    for (int o = 16; o; o >>= 1) s += __shfl_down_sync(0xffffffffu, s, o);
    if (lane == 0) g_nhn[gw] = -0.5f * s;
}

// ---------------------------------------------------------------------------
// Fused mma.sync GEMM + per-j-half top-2 of score = dot - 0.5*|m|^2.
// 144 blocks: (class, M-tile 128). 256 threads = 8 warps: 4(M) x 2(N),
// warp tile 32x64. K=64. Main product A0*B0 in f32-acc MMA; small cross
// products A1*B0 and A0*B1 accumulate together in f16-acc MMA (2x rate).
// B + negated half-norms double-buffered in 256-j chunks (1 barrier/chunk).
// ---------------------------------------------------------------------------
__global__ void __launch_bounds__(GEMM_THREADS, 1) gemm_argmin() {
    extern __shared__ unsigned char smc[];
    unsigned sb = (unsigned)__cvta_generic_to_shared(smc);
    const int tid = threadIdx.x;
    const int wid = tid >> 5, lane = tid & 31;
    const int wm = wid >> 1, wn = wid & 1;
    const int tu = lane >> 2, cfr = lane & 3;
    const int cls = blockIdx.x / BPC;
    const int tile_m = blockIdx.x - cls * BPC;

    // chunk permutation offsets (thread-constant: row&7 == n&7 == tu)
    const int ch0 = (cfr * 2 + 0 + tu) & 7;
    const int ch1 = (cfr * 2 + 1 + tu) & 7;

    const unsigned char* gB = g_Bh + ((size_t)(cls * NCH) * 2) * CHUNK_B;

    // one-time: A splits (32KB) + chunk 0 (64KB B + 1KB norms), one group
    {
        const uint4* as =
            (const uint4*)(g_Ah + (size_t)((cls * BPC + tile_m) * 2) * TILE_B);
        for (int i = tid; i < 2048; i += GEMM_THREADS)
            cpa16(sb + SM_A + i * 16, as + i);
        const uint4* bs = (const uint4*)gB;
        const uint4* ns = (const uint4*)g_nhn;
        for (int i = tid; i < 4160; i += GEMM_THREADS)
            cpa16(sb + SM_B + i * 16, (i < 4096) ? (bs + i) : (ns + i - 4096));
        cpa_commit();
    }
    cpa_wait0();
    __syncthreads();

    // hoist BOTH A split fragment sets (tile-constant)
    uint4 a0f[2][2][2], a1f[2][2][2];
    {
        const uint4* Ap0 = (const uint4*)(smc + SM_A);
        const uint4* Ap1 = (const uint4*)(smc + SM_A + TILE_B);
        #pragma unroll
        for (int mt = 0; mt < 2; mt++)
            #pragma unroll
            for (int rr = 0; rr < 2; rr++) {
                int row = wm * 32 + mt * 16 + rr * 8 + tu;
                a0f[mt][rr][0] = Ap0[row * 8 + ch0];
                a0f[mt][rr][1] = Ap0[row * 8 + ch1];
                a1f[mt][rr][0] = Ap1[row * 8 + ch0];
                a1f[mt][rr][1] = Ap1[row * 8 + ch1];
            }
    }

    float rb1[4], rb2[4];
    int   ri1[4], ri2[4];
    #pragma unroll
    for (int x = 0; x < 4; x++) {
        rb1[x] = -3.4e38f; rb2[x] = -3.4e38f;
        ri1[x] = 0x7fffffff; ri2[x] = 0x7fffffff;
    }

    for (int c = 0; c < NCH; c++) {
        // prefetch chunk c+1 (overlaps compute)
        if (c + 1 < NCH) {
            const uint4* bs = (const uint4*)(gB + (size_t)(c + 1) * 2 * CHUNK_B);
            const uint4* ns = (const uint4*)(g_nhn + (c + 1) * 256);
            unsigned dst = sb + SM_B + ((c + 1) & 1) * BUFST;
            for (int i = tid; i < 4160; i += GEMM_THREADS)
                cpa16(dst + i * 16, (i < 4096) ? (bs + i) : (ns + i - 4096));
            cpa_commit();
        }

        const unsigned char* buf = smc + SM_B + (c & 1) * BUFST;
        const uint4*  Bb0 = (const uint4*)buf;             // split 0
        const uint4*  Bb1 = (const uint4*)(buf + CHUNK_B); // split 1
        const float2* hnp = (const float2*)(buf + 2 * CHUNK_B);

        #pragma unroll
        for (int tt = 0; tt < 2; tt++) {
            float acc[2][8][4];            // f32 main product
            unsigned acch[2][8][2];        // f16x2 cross products
            #pragma unroll
            for (int mt = 0; mt < 2; mt++)
                #pragma unroll
                for (int nt = 0; nt < 8; nt++) {
                    #pragma unroll
                    for (int q = 0; q < 4; q++) acc[mt][nt][q] = 0.f;
                    acch[mt][nt][0] = 0u; acch[mt][nt][1] = 0u;
                }

            // ---- B split 0: A0*B0 (f32 acc) + A1*B0 (f16 acc)
            #pragma unroll
            for (int ng = 0; ng < 2; ng++) {
                uint4 bp[4][2];
                #pragma unroll
                for (int i = 0; i < 4; i++) {
                    int n = tt * 128 + wn * 64 + (ng * 4 + i) * 8 + tu;
                    bp[i][0] = Bb0[n * 8 + ch0];
                    bp[i][1] = Bb0[n * 8 + ch1];
                }
                #pragma unroll
                for (int kk = 0; kk < 4; kk++)
                    #pragma unroll
                    for (int mt = 0; mt < 2; mt++) {
                        unsigned a0 = ((const unsigned*)&a0f[mt][0][0])[kk];
                        unsigned a1 = ((const unsigned*)&a0f[mt][1][0])[kk];
                        unsigned a2 = ((const unsigned*)&a0f[mt][0][1])[kk];
                        unsigned a3 = ((const unsigned*)&a0f[mt][1][1])[kk];
                        #pragma unroll
                        for (int i = 0; i < 4; i++) {
                            int nt = ng * 4 + i;
                            mma16816(acc[mt][nt][0], acc[mt][nt][1],
                                     acc[mt][nt][2], acc[mt][nt][3],
                                     a0, a1, a2, a3,
                                     ((const unsigned*)&bp[i][0])[kk],
                                     ((const unsigned*)&bp[i][1])[kk]);
                        }
                    }
                #pragma unroll
                for (int kk = 0; kk < 4; kk++)
                    #pragma unroll
                    for (int mt = 0; mt < 2; mt++) {
                        unsigned a0 = ((const unsigned*)&a1f[mt][0][0])[kk];
                        unsigned a1 = ((const unsigned*)&a1f[mt][1][0])[kk];
                        unsigned a2 = ((const unsigned*)&a1f[mt][0][1])[kk];
                        unsigned a3 = ((const unsigned*)&a1f[mt][1][1])[kk];
                        #pragma unroll
                        for (int i = 0; i < 4; i++) {
                            int nt = ng * 4 + i;
                            mma16816h(acch[mt][nt][0], acch[mt][nt][1],
                                      a0, a1, a2, a3,
                                      ((const unsigned*)&bp[i][0])[kk],
                                      ((const unsigned*)&bp[i][1])[kk]);
                        }
                    }
            }
            // ---- B split 1: A0*B1 (f16 acc, same accumulators)
            #pragma unroll
            for (int ng = 0; ng < 2; ng++) {
                uint4 bp[4][2];
                #pragma unroll
                for (int i = 0; i < 4; i++) {
                    int n = tt * 128 + wn * 64 + (ng * 4 + i) * 8 + tu;
                    bp[i][0] = Bb1[n * 8 + ch0];
                    bp[i][1] = Bb1[n * 8 + ch1];
                }
                #pragma unroll
                for (int kk = 0; kk < 4; kk++)
                    #pragma unroll
                    for (int mt = 0; mt < 2; mt++) {
                        unsigned a0 = ((const unsigned*)&a0f[mt][0][0])[kk];
                        unsigned a1 = ((const unsigned*)&a0f[mt][1][0])[kk];
                        unsigned a2 = ((const unsigned*)&a0f[mt][0][1])[kk];
                        unsigned a3 = ((const unsigned*)&a0f[mt][1][1])[kk];
                        #pragma unroll
                        for (int i = 0; i < 4; i++) {
                            int nt = ng * 4 + i;
                            mma16816h(acch[mt][nt][0], acch[mt][nt][1],
                                      a0, a1, a2, a3,
                                      ((const unsigned*)&bp[i][0])[kk],
                                      ((const unsigned*)&bp[i][1])[kk]);
                        }
                    }
            }

            // ---- epilogue: score = acc + cross + nhn; fmax tree; rare rescan
            int jt = c * 256 + tt * 128;
            #pragma unroll
            for (int nt = 0; nt < 8; nt++) {
                float2 hn = hnp[tt * 64 + wn * 32 + nt * 4 + cfr];  // negated
                #pragma unroll
                for (int mt = 0; mt < 2; mt++) {
                    float2 c01 = __half22float2(
                        *reinterpret_cast<__half2*>(&acch[mt][nt][0]));
                    float2 c23 = __half22float2(
                        *reinterpret_cast<__half2*>(&acch[mt][nt][1]));
                    acc[mt][nt][0] += c01.x + hn.x;
                    acc[mt][nt][1] += c01.y + hn.y;
                    acc[mt][nt][2] += c23.x + hn.x;
                    acc[mt][nt][3] += c23.y + hn.y;
                }
            }
            #pragma unroll
            for (int mt = 0; mt < 2; mt++)
                #pragma unroll
                for (int rr = 0; rr < 2; rr++) {
                    int ctx = mt * 2 + rr;
                    float sv[16];
                    #pragma unroll
                    for (int la = 0; la < 16; la++)
                        sv[la] = acc[mt][la >> 1][rr * 2 + (la & 1)];
                    #pragma unroll
                    for (int st = 8; st; st >>= 1)
                        #pragma unroll
                        for (int i = 0; i < st; i++)
                            sv[i] = fmaxf(sv[i], sv[i + st]);
                    float mx = sv[0];
                    if (mx > rb2[ctx]) {          // rare
                        int la = 0;
                        #pragma unroll
                        for (int i = 15; i >= 0; i--)
                            if (acc[mt][i >> 1][rr * 2 + (i & 1)] == mx) la = i;
                        int jarg = jt + wn * 64 + (la >> 1) * 8 +
                                   cfr * 2 + (la & 1);
                        if (mx > rb1[ctx]) {
                            rb2[ctx] = rb1[ctx]; ri2[ctx] = ri1[ctx];
                            rb1[ctx] = mx; ri1[ctx] = jarg;
                        } else { rb2[ctx] = mx; ri2[ctx] = jarg; }
                    }
                }
        }

        // chunk c+1 copy complete AND all warps done with buf (c&1)
        if (c + 1 < NCH) {
            cpa_wait0();
            __syncthreads();
        }
    }

    // merge top-2 across the 4 lanes (cfr groups) sharing each row
    #pragma unroll
    for (int ctx = 0; ctx < 4; ctx++) {
        #pragma unroll
        for (int m = 1; m <= 2; m <<= 1) {
            float ob1 = __shfl_xor_sync(0xffffffffu, rb1[ctx], m);
            int   oi1 = __shfl_xor_sync(0xffffffffu, ri1[ctx], m);
            float ob2 = __shfl_xor_sync(0xffffffffu, rb2[ctx], m);
            int   oi2 = __shfl_xor_sync(0xffffffffu, ri2[ctx], m);
            if (rank_gt(ob1, oi1, rb1[ctx], ri1[ctx])) {
                if (rank_gt(rb1[ctx], ri1[ctx], ob2, oi2)) {
                    rb2[ctx] = rb1[ctx]; ri2[ctx] = ri1[ctx];
                } else { rb2[ctx] = ob2; ri2[ctx] = oi2; }
                rb1[ctx] = ob1; ri1[ctx] = oi1;
            } else if (rank_gt(ob1, oi1, rb2[ctx], ri2[ctx])) {
                rb2[ctx] = ob1; ri2[ctx] = oi1;
            }
        }
    }
    // each wn-warp writes ITS j-half's top-2 into its own int2 slot
    if (cfr == 0) {
        #pragma unroll
        for (int ctx = 0; ctx < 4; ctx++) {
            int mt = ctx >> 1, rr = ctx & 1;
            int m_local = wm * 32 + mt * 16 + rr * 8 + tu;
            int qc = tile_m * 128 + m_local;
            if (qc < MC) {
                int py = cls >> 1, px = cls & 1;
                int a = qc / NC, b = qc - a * NC;
                int q = (py + 2 * a) * L1 + (px + 2 * b);
                int2 cd; cd.x = ri1[ctx]; cd.y = ri2[ctx];
                ((int2*)&g_cand4[q])[wn] = cd;
            }
        }
    }
}

// ---------------------------------------------------------------------------
// Repair: exact fp32 evaluation of the 4 candidates per query (top-2 from
// each j-half), score-max form; identical decisions to the validated R4 path.
// ---------------------------------------------------------------------------
__global__ void repair(const float* __restrict__ image) {
    int q = blockIdx.x * 256 + threadIdx.x;
    if (q >= MQ) return;
    int4 cd = g_cand4[q];
    int cands[4] = {cd.x, cd.y, cd.z, cd.w};
    int r = q / L1, c = q - r * L1;
    int cls = (r & 1) * 2 + (c & 1);
    int by = (r - PAD) >> 1, bx = (c - PAD) >> 1;
    float x[KC];
    #pragma unroll
    for (int s = 0; s < KC; s++) {
        int sy = s >> 3, sx = s & 7;
        int yy = by + sy, xx = bx + sx;
        x[s] = ((unsigned)yy < 64u && (unsigned)xx < 64u)
                   ? image[yy * 64 + xx] : 0.f;
    }
    float best = -3.4e38f; int bi = 0x7fffffff;
    #pragma unroll
    for (int ci = 0; ci < 4; ci++) {
        int cj = cands[ci];
        const float* mm = g_m2f + ((size_t)(cls * NMEM + cj) << 6);
        float d = 0.f;
        #pragma unroll
        for (int s = 0; s < KC; s++) d += x[s] * mm[s];
        float sc = g_nhn[cj] + d;     // dot - 0.5|m|^2  (maximize)
        if (sc > best || (sc == best && cj < bi)) { best = sc; bi = cj; }
    }
    g_idx[q] = bi;
}

// ---------------------------------------------------------------------------
// Reconstruction: out_raw[a][b] = acc[2a+10][2b+10]
// ---------------------------------------------------------------------------
__global__ void recon(const float* __restrict__ mem) {
    int t = blockIdx.x * 256 + threadIdx.x;      // 0..4095
    if (t >= 4096) return;
    int a = t >> 6, b = t & 63;
    int y = 2 * a + PAD, x = 2 * b + PAD;
    float s = 0.f;
    #pragma unroll
    for (int i = 0; i < KSZ; i++) {
        int ry = y - i;
        if ((unsigned)ry >= (unsigned)L1) continue;
        int rowbase = ry * L1;
        #pragma unroll
        for (int j = 0; j < KSZ; j++) {
            int rx = x - j;
            if ((unsigned)rx >= (unsigned)L1) continue;
            s += mem[g_idx[rowbase + rx] * KDIM + i * KSZ + j];
        }
    }
    g_raw[t] = s;
}

// max-normalize (single block)
__global__ void normalize_out(float* __restrict__ out) {
    __shared__ float smx[256];
    int tid = threadIdx.x;
    float mx = -3.4e38f;
    for (int i = tid; i < 4096; i += 256) mx = fmaxf(mx, g_raw[i]);
    smx[tid] = mx;
    __syncthreads();
    for (int o = 128; o; o >>= 1) {
        if (tid < o) smx[tid] = fmaxf(smx[tid], smx[tid + o]);
        __syncthreads();
    }
    float m = smx[0];
    for (int i = tid; i < 4096; i += 256) out[i] = g_raw[i] / m;
}

// ---------------------------------------------------------------------------
extern "C" void kernel_launch(void* const* d_in, const int* in_sizes, int n_in,
                              void* d_out, int out_size) {
    const float* image = (const float*)d_in[0];   // 64*64
    const float* mem   = (const float*)d_in[1];   // 16384*225
    float* out = (float*)d_out;                   // 64*64

    cudaFuncSetAttribute(gemm_argmin,
                         cudaFuncAttributeMaxDynamicSharedMemorySize,
                         GEMM_SMEM);

    {
        int n = 4 * BPC * 128 * 32;
        prep_Ah<<<(n + 255) / 256, 256>>>(image);
    }
    {
        int n = 4 * NMEM * 32;
        prep_Bh<<<(n + 255) / 256, 256>>>(mem);
    }
    prep_norms<<<(NMEM * 32) / 256, 256>>>(mem);

    gemm_argmin<<<GEMM_BLOCKS, GEMM_THREADS, GEMM_SMEM>>>();

    repair<<<(MQ + 255) / 256, 256>>>(image);
    recon<<<16, 256>>>(mem);
    normalize_out<<<1, 256>>>(out);
}

// round 16
// speedup vs baseline: 1.0637x; 1.0637x over previous
#include <cuda_runtime.h>
#include <cuda_fp16.h>

// Problem constants
#define KSZ   15
#define PAD   10
#define L1    134
#define MQ    17956          // L1*L1 queries
#define NMEM  16384
#define KDIM  225
#define NC    67             // per-axis queries per parity class
#define MC    4489           // queries per class
#define KC    64             // compressed K (8x8 source window)
#define BPC   71             // M-tiles (of 64) per class (71*64=4544)
#define GEMM_BLOCKS (4*BPC)  // 284
#define GEMM_THREADS 128
#define NT    128            // 64-j tiles per warp (8192 j per warp)
#define SLOT  8192           // bytes per B slice (64 rows x 128B, one split)
// smem: A tile (16KB = 64 rows x 128B x 2 splits) | 4 warps x 3 ring slots
#define SM_A   0
#define SM_RING 16384
#define GEMM_SMEM (16384 + 4*3*SLOT)   // 114688 -> 2 CTAs/SM

// -------- device scratch -----------------------------------------------------
__device__ __align__(16) unsigned char g_Ah[4 * BPC * 2 * SLOT];     // fp16 A
__device__ __align__(16) unsigned char g_Bh[4 * 256 * 2 * SLOT];     // fp16 B
__device__ __align__(16) float g_m2f[4 * NMEM * KC];  // fp32 compressed mem
__device__ __align__(16) float g_nhn[NMEM];           // negated half norms
__device__ __align__(16) int4 g_cand4[MQ];            // top-2 per j-half (xy/zw)
__device__ int   g_idx[MQ];
__device__ float g_raw[64 * 64];

// -------- helpers ------------------------------------------------------------
__device__ __forceinline__ void split2h(float v, unsigned short& h0,
                                        unsigned short& h1) {
    __half a = __float2half_rn(v);
    float r = v - __half2float(a);
    __half b = __float2half_rn(r);
    h0 = __half_as_ushort(a);
    h1 = __half_as_ushort(b);
}

__device__ __forceinline__ void mma16816(float& d0, float& d1, float& d2, float& d3,
                                         unsigned a0, unsigned a1, unsigned a2,
                                         unsigned a3, unsigned b0, unsigned b1) {
    asm volatile(
        "mma.sync.aligned.m16n8k16.row.col.f32.f16.f16.f32 "
        "{%0,%1,%2,%3},{%4,%5,%6,%7},{%8,%9},{%0,%1,%2,%3};"
        : "+f"(d0), "+f"(d1), "+f"(d2), "+f"(d3)
        : "r"(a0), "r"(a1), "r"(a2), "r"(a3), "r"(b0), "r"(b1));
}

__device__ __forceinline__ void cpa16(unsigned dst, const void* src) {
    asm volatile("cp.async.cg.shared.global [%0], [%1], 16;" :: "r"(dst), "l"(src));
}
__device__ __forceinline__ void cpa_commit() {
    asm volatile("cp.async.commit_group;" ::: "memory");
}
__device__ __forceinline__ void cpa_wait0() {
    asm volatile("cp.async.wait_group 0;" ::: "memory");
}
__device__ __forceinline__ void cpa_wait2() {
    asm volatile("cp.async.wait_group 2;" ::: "memory");
}

// rank-before: larger score first; ties -> lower index
__device__ __forceinline__ bool rank_gt(float a, int ia, float b, int ib) {
    return (a > b) || (a == b && ia < ib);
}

// ---------------------------------------------------------------------------
// slot sum (validated in R4)
// ---------------------------------------------------------------------------
__device__ __forceinline__ float slotsum(const float* __restrict__ row,
                                         int py, int px, int sy, int sx) {
    int i0 = py ? 2 * sy - 1 : 2 * sy;
    int i1 = i0 + 1;
    int j0 = px ? 2 * sx - 1 : 2 * sx;
    int j1 = j0 + 1;
    float s = 0.f;
    if ((unsigned)i0 < 15u) {
        if ((unsigned)j0 < 15u) s += row[i0 * KSZ + j0];
        if ((unsigned)j1 < 15u) s += row[i0 * KSZ + j1];
    }
    if ((unsigned)i1 < 15u) {
        if ((unsigned)j0 < 15u) s += row[i1 * KSZ + j0];
        if ((unsigned)j1 < 15u) s += row[i1 * KSZ + j1];
    }
    return s;
}

// chunk-permuted in-row byte offset for logical k (0..63)
__device__ __forceinline__ int kpos(int row, int k) {
    int c = (k >> 1) & 3, h = (k >> 3) & 1, kk = k >> 4;
    int chunk = ((c * 2 + h + row) & 7);
    return chunk * 16 + kk * 4 + (k & 1) * 2;
}

// ---------------------------------------------------------------------------
// Prep B: compressed mem -> 2 fp16 splits in 64-row tiles (8KB per split)
// ---------------------------------------------------------------------------
__global__ void prep_Bh(const float* __restrict__ mem) {
    int e = blockIdx.x * 256 + threadIdx.x;
    if (e >= 4 * NMEM * 32) return;
    int k2  = e & 31;
    int j   = (e >> 5) & (NMEM - 1);
    int cls = e >> 19;
    int py = cls >> 1, px = cls & 1;
    int s0 = 2 * k2, sy = s0 >> 3, sx = s0 & 7;
    const float* row = mem + j * KDIM;
    float vx = slotsum(row, py, px, sy, sx);
    float vy = slotsum(row, py, px, sy, sx + 1);

    *(float2*)&g_m2f[((size_t)(cls * NMEM + j) << 6) + s0] = make_float2(vx, vy);

    unsigned short x0, x1, y0, y1;
    split2h(vx, x0, x1);
    split2h(vy, y0, y1);
    int r = j & 63;
    int off = kpos(r, s0);
    size_t base = ((size_t)(cls * 256 + (j >> 6)) * 2) * SLOT + (size_t)r * 128;
    ushort2 v0; v0.x = x0; v0.y = y0;
    ushort2 v1; v1.x = x1; v1.y = y1;
    *(ushort2*)(g_Bh + base + off) = v0;
    *(ushort2*)(g_Bh + base + SLOT + off) = v1;
}

// ---------------------------------------------------------------------------
// Prep A: compressed queries -> 2 fp16 splits in 64-row tiles
// ---------------------------------------------------------------------------
__global__ void prep_Ah(const float* __restrict__ image) {
    int e = blockIdx.x * 256 + threadIdx.x;
    if (e >= 4 * BPC * 64 * 32) return;
    int k2  = e & 31;
    int r   = (e >> 5) & 63;
    int r1  = e >> 11;                  // cls*BPC + tile
    int tile = r1 % BPC;
    int cls  = r1 / BPC;
    int py = cls >> 1, px = cls & 1;
    float vx = 0.f, vy = 0.f;
    int qc = tile * 64 + r;
    int s0 = 2 * k2, sy = s0 >> 3, sx = s0 & 7;
    if (qc < MC) {
        int a = qc / NC, b = qc - a * NC;
        int by = ((py + 2 * a) - PAD) >> 1;
        int bx = ((px + 2 * b) - PAD) >> 1;
        int yy = by + sy;
        if ((unsigned)yy < 64u) {
            int x0i = bx + sx, x1i = x0i + 1;
            if ((unsigned)x0i < 64u) vx = image[yy * 64 + x0i];
            if ((unsigned)x1i < 64u) vy = image[yy * 64 + x1i];
        }
    }
    unsigned short x0, x1, y0, y1;
    split2h(vx, x0, x1);
    split2h(vy, y0, y1);
    int off = kpos(r, s0);
    size_t base = (size_t)(r1 * 2) * SLOT + (size_t)r * 128;
    ushort2 v0; v0.x = x0; v0.y = y0;
    ushort2 v1; v1.x = x1; v1.y = y1;
    *(ushort2*)(g_Ah + base + off) = v0;
    *(ushort2*)(g_Ah + base + SLOT + off) = v1;
}

// Prep: NEGATED half squared norms (-0.5*|m|^2), one warp per row
__global__ void prep_norms(const float* __restrict__ mem) {
    int gw   = (blockIdx.x * blockDim.x + threadIdx.x) >> 5;
    int lane = threadIdx.x & 31;
    if (gw >= NMEM) return;
    const float* row = mem + gw * KDIM;
    float s = 0.f;
    for (int k = lane; k < KDIM; k += 32) { float v = row[k]; s += v * v; }
    #pragma unroll
    for (int o = 16; o; o >>= 1) s += __shfl_down_sync(0xffffffffu, s, o);
    if (lane == 0) g_nhn[gw] = -0.5f * s;
}

// ---------------------------------------------------------------------------
// Fused mma.sync GEMM + per-j-half top-2, BARRIER-FREE main loop.
// 284 blocks: (class, M-tile 64). 128 threads = 4 warps; warp (wm, jr) owns
// rows wm*32..+32 and j-range jr*8192..+8192 (disjoint -> no B duplication).
// Each warp: private 3x8KB smem ring, private cp.async groups (per-thread
// wait_group), 64-j tiles, 192 MMA/tile, norms via LDG. 2 CTAs/SM.
// ---------------------------------------------------------------------------
__global__ void __launch_bounds__(GEMM_THREADS, 2) gemm_argmin() {
    extern __shared__ unsigned char smc[];
    unsigned sb = (unsigned)__cvta_generic_to_shared(smc);
    const int tid = threadIdx.x;
    const int wid = tid >> 5, lane = tid & 31;
    const int wm = wid & 1, jr = wid >> 1;
    const int tu = lane >> 2, cfr = lane & 3;
    const int cls = blockIdx.x / BPC;
    const int tile_m = blockIdx.x - cls * BPC;

    const int ch0 = (cfr * 2 + 0 + tu) & 7;
    const int ch1 = (cfr * 2 + 1 + tu) & 7;

    // cooperative A tile load (16KB), the ONLY block barrier
    {
        const uint4* as =
            (const uint4*)(g_Ah + (size_t)((cls * BPC + tile_m) * 2) * SLOT);
        for (int i = tid; i < 1024; i += GEMM_THREADS)
            cpa16(sb + SM_A + i * 16, as + i);
        cpa_commit();
        cpa_wait0();
    }
    __syncthreads();

    // hoist A fragments (both splits), rows wm*32 .. +32
    uint4 a0f[2][2][2], a1f[2][2][2];
    {
        const uint4* Ap0 = (const uint4*)(smc + SM_A);
        const uint4* Ap1 = (const uint4*)(smc + SM_A + SLOT);
        #pragma unroll
        for (int mt = 0; mt < 2; mt++)
            #pragma unroll
            for (int rr = 0; rr < 2; rr++) {
                int row = wm * 32 + mt * 16 + rr * 8 + tu;
                a0f[mt][rr][0] = Ap0[row * 8 + ch0];
                a0f[mt][rr][1] = Ap0[row * 8 + ch1];
                a1f[mt][rr][0] = Ap1[row * 8 + ch0];
                a1f[mt][rr][1] = Ap1[row * 8 + ch1];
            }
    }

    const unsigned ringb = sb + SM_RING + wid * (3 * SLOT);
    const unsigned char* ringp = smc + SM_RING + wid * (3 * SLOT);
    const unsigned char* gBc =
        g_Bh + ((size_t)(cls * 256 + jr * NT) * 2) * SLOT;

    // warp-private slice copy: 8KB, 16 cpa16 per lane, one commit group
    auto copy_slice = [&](int slot, const unsigned char* src) {
        unsigned dst = ringb + slot * SLOT + lane * 16;
        const unsigned char* s = src + lane * 16;
        #pragma unroll
        for (int p = 0; p < 16; p++)
            cpa16(dst + p * 512, s + p * 512);
        cpa_commit();
    };

    // prime pipeline: s0(0)->slot0, s1(0)->slot1, s0(1)->slot2
    copy_slice(0, gBc);
    copy_slice(1, gBc + SLOT);
    copy_slice(2, gBc + 2 * SLOT);

    float rb1[4], rb2[4];
    int   ri1[4], ri2[4];
    #pragma unroll
    for (int x = 0; x < 4; x++) {
        rb1[x] = -3.4e38f; rb2[x] = -3.4e38f;
        ri1[x] = 0x7fffffff; ri2[x] = 0x7fffffff;
    }

    const int jbase = jr * 8192;

    for (int t = 0; t < NT; t++) {
        int s0slot = (2 * t) % 3;
        int s1slot = (2 * t + 1) % 3;

        cpa_wait2();                 // s0(t) ready (2 groups may remain)

        // prefetch norms for this tile (L2 hit, hidden under MMAs)
        int j0 = jbase + t * 64;
        float2 nrm[8];
        #pragma unroll
        for (int nt = 0; nt < 8; nt++)
            nrm[nt] = __ldg((const float2*)&g_nhn[j0 + nt * 8 + cfr * 2]);

        float acc[2][8][4];
        #pragma unroll
        for (int mt = 0; mt < 2; mt++)
            #pragma unroll
            for (int nt = 0; nt < 8; nt++)
                #pragma unroll
                for (int q = 0; q < 4; q++) acc[mt][nt][q] = 0.f;

        // ---- split 0 passes: A0*B0 and A1*B0
        {
            const uint4* Bs = (const uint4*)(ringp + s0slot * SLOT);
            #pragma unroll
            for (int ng = 0; ng < 2; ng++) {
                uint4 bp[4][2];
                #pragma unroll
                for (int i = 0; i < 4; i++) {
                    int n = (ng * 4 + i) * 8 + tu;
                    bp[i][0] = Bs[n * 8 + ch0];
                    bp[i][1] = Bs[n * 8 + ch1];
                }
                #pragma unroll
                for (int kk = 0; kk < 4; kk++)
                    #pragma unroll
                    for (int mt = 0; mt < 2; mt++) {
                        unsigned a0 = ((const unsigned*)&a0f[mt][0][0])[kk];
                        unsigned a1 = ((const unsigned*)&a0f[mt][1][0])[kk];
                        unsigned a2 = ((const unsigned*)&a0f[mt][0][1])[kk];
                        unsigned a3 = ((const unsigned*)&a0f[mt][1][1])[kk];
                        #pragma unroll
                        for (int i = 0; i < 4; i++) {
                            int nt = ng * 4 + i;
                            mma16816(acc[mt][nt][0], acc[mt][nt][1],
                                     acc[mt][nt][2], acc[mt][nt][3],
                                     a0, a1, a2, a3,
                                     ((const unsigned*)&bp[i][0])[kk],
                                     ((const unsigned*)&bp[i][1])[kk]);
                        }
                    }
                #pragma unroll
                for (int kk = 0; kk < 4; kk++)
                    #pragma unroll
                    for (int mt = 0; mt < 2; mt++) {
                        unsigned a0 = ((const unsigned*)&a1f[mt][0][0])[kk];
                        unsigned a1 = ((const unsigned*)&a1f[mt][1][0])[kk];
                        unsigned a2 = ((const unsigned*)&a1f[mt][0][1])[kk];
                        unsigned a3 = ((const unsigned*)&a1f[mt][1][1])[kk];
                        #pragma unroll
                        for (int i = 0; i < 4; i++) {
                            int nt = ng * 4 + i;
                            mma16816(acc[mt][nt][0], acc[mt][nt][1],
                                     acc[mt][nt][2], acc[mt][nt][3],
                                     a0, a1, a2, a3,
                                     ((const unsigned*)&bp[i][0])[kk],
                                     ((const unsigned*)&bp[i][1])[kk]);
                        }
                    }
            }
        }

        // refill s0(t)'s slot with s1(t+1)
        {
            int tn = (t + 1 < NT) ? t + 1 : NT - 1;
            copy_slice(s0slot, gBc + ((size_t)tn * 2 + 1) * SLOT);
        }

        cpa_wait2();                 // s1(t) ready

        // ---- split 1 pass: A0*B1
        {
            const uint4* Bs = (const uint4*)(ringp + s1slot * SLOT);
            #pragma unroll
            for (int ng = 0; ng < 2; ng++) {
                uint4 bp[4][2];
                #pragma unroll
                for (int i = 0; i < 4; i++) {
                    int n = (ng * 4 + i) * 8 + tu;
                    bp[i][0] = Bs[n * 8 + ch0];
                    bp[i][1] = Bs[n * 8 + ch1];
                }
                #pragma unroll
                for (int kk = 0; kk < 4; kk++)
                    #pragma unroll
                    for (int mt = 0; mt < 2; mt++) {
                        unsigned a0 = ((const unsigned*)&a0f[mt][0][0])[kk];
                        unsigned a1 = ((const unsigned*)&a0f[mt][1][0])[kk];
                        unsigned a2 = ((const unsigned*)&a0f[mt][0][1])[kk];
                        unsigned a3 = ((const unsigned*)&a0f[mt][1][1])[kk];
                        #pragma unroll
                        for (int i = 0; i < 4; i++) {
                            int nt = ng * 4 + i;
                            mma16816(acc[mt][nt][0], acc[mt][nt][1],
                                     acc[mt][nt][2], acc[mt][nt][3],
                                     a0, a1, a2, a3,
                                     ((const unsigned*)&bp[i][0])[kk],
                                     ((const unsigned*)&bp[i][1])[kk]);
                        }
                    }
            }
        }

        // refill s1(t)'s slot with s0(t+2)
        {
            int tn = (t + 2 < NT) ? t + 2 : NT - 1;
            copy_slice(s1slot, gBc + (size_t)tn * 2 * SLOT);
        }

        // ---- epilogue: score = dot + nhn; fmax tree; rare indexed rescan
        #pragma unroll
        for (int nt = 0; nt < 8; nt++)
            #pragma unroll
            for (int mt = 0; mt < 2; mt++) {
                acc[mt][nt][0] += nrm[nt].x;
                acc[mt][nt][1] += nrm[nt].y;
                acc[mt][nt][2] += nrm[nt].x;
                acc[mt][nt][3] += nrm[nt].y;
            }
        #pragma unroll
        for (int mt = 0; mt < 2; mt++)
            #pragma unroll
            for (int rr = 0; rr < 2; rr++) {
                int ctx = mt * 2 + rr;
                float sv[16];
                #pragma unroll
                for (int la = 0; la < 16; la++)
                    sv[la] = acc[mt][la >> 1][rr * 2 + (la & 1)];
                #pragma unroll
                for (int st = 8; st; st >>= 1)
                    #pragma unroll
                    for (int i = 0; i < st; i++)
                        sv[i] = fmaxf(sv[i], sv[i + st]);
                float mx = sv[0];
                if (mx > rb2[ctx]) {          // rare
                    int la = 0;
                    #pragma unroll
                    for (int i = 15; i >= 0; i--)
                        if (acc[mt][i >> 1][rr * 2 + (i & 1)] == mx) la = i;
                    int jarg = j0 + (la >> 1) * 8 + cfr * 2 + (la & 1);
                    if (mx > rb1[ctx]) {
                        rb2[ctx] = rb1[ctx]; ri2[ctx] = ri1[ctx];
                        rb1[ctx] = mx; ri1[ctx] = jarg;
                    } else { rb2[ctx] = mx; ri2[ctx] = jarg; }
                }
            }
    }

    // merge top-2 across the 4 lanes (cfr groups) sharing each row
    #pragma unroll
    for (int ctx = 0; ctx < 4; ctx++) {
        #pragma unroll
        for (int m = 1; m <= 2; m <<= 1) {
            float ob1 = __shfl_xor_sync(0xffffffffu, rb1[ctx], m);
            int   oi1 = __shfl_xor_sync(0xffffffffu, ri1[ctx], m);
            float ob2 = __shfl_xor_sync(0xffffffffu, rb2[ctx], m);
            int   oi2 = __shfl_xor_sync(0xffffffffu, ri2[ctx], m);
            if (rank_gt(ob1, oi1, rb1[ctx], ri1[ctx])) {
                if (rank_gt(rb1[ctx], ri1[ctx], ob2, oi2)) {
                    rb2[ctx] = rb1[ctx]; ri2[ctx] = ri1[ctx];
                } else { rb2[ctx] = ob2; ri2[ctx] = oi2; }
                rb1[ctx] = ob1; ri1[ctx] = oi1;
            } else if (rank_gt(ob1, oi1, rb2[ctx], ri2[ctx])) {
                rb2[ctx] = ob1; ri2[ctx] = oi1;
            }
        }
    }
    // each warp writes ITS j-half's top-2 into its own int2 slot
    if (cfr == 0) {
        #pragma unroll
        for (int ctx = 0; ctx < 4; ctx++) {
            int mt = ctx >> 1, rr = ctx & 1;
            int m_local = wm * 32 + mt * 16 + rr * 8 + tu;
            int qc = tile_m * 64 + m_local;
            if (qc < MC) {
                int py = cls >> 1, px = cls & 1;
                int a = qc / NC, b = qc - a * NC;
                int q = (py + 2 * a) * L1 + (px + 2 * b);
                int2 cd; cd.x = ri1[ctx]; cd.y = ri2[ctx];
                ((int2*)&g_cand4[q])[jr] = cd;
            }
        }
    }
}

// ---------------------------------------------------------------------------
// Repair: exact fp32 evaluation of the 4 candidates per query (top-2 from
// each j-half), score-max form; identical decisions to the validated R4 path.
// ---------------------------------------------------------------------------
__global__ void repair(const float* __restrict__ image) {
    int q = blockIdx.x * 256 + threadIdx.x;
    if (q >= MQ) return;
    int4 cd = g_cand4[q];
    int cands[4] = {cd.x, cd.y, cd.z, cd.w};
    int r = q / L1, c = q - r * L1;
    int cls = (r & 1) * 2 + (c & 1);
    int by = (r - PAD) >> 1, bx = (c - PAD) >> 1;
    float x[KC];
    #pragma unroll
    for (int s = 0; s < KC; s++) {
        int sy = s >> 3, sx = s & 7;
        int yy = by + sy, xx = bx + sx;
        x[s] = ((unsigned)yy < 64u && (unsigned)xx < 64u)
                   ? image[yy * 64 + xx] : 0.f;
    }
    float best = -3.4e38f; int bi = 0x7fffffff;
    #pragma unroll
    for (int ci = 0; ci < 4; ci++) {
        int cj = cands[ci];
        const float* mm = g_m2f + ((size_t)(cls * NMEM + cj) << 6);
        float d = 0.f;
        #pragma unroll
        for (int s = 0; s < KC; s++) d += x[s] * mm[s];
        float sc = g_nhn[cj] + d;     // dot - 0.5|m|^2  (maximize)
        if (sc > best || (sc == best && cj < bi)) { best = sc; bi = cj; }
    }
    g_idx[q] = bi;
}

// ---------------------------------------------------------------------------
// Reconstruction: out_raw[a][b] = acc[2a+10][2b+10]
// ---------------------------------------------------------------------------
__global__ void recon(const float* __restrict__ mem) {
    int t = blockIdx.x * 256 + threadIdx.x;      // 0..4095
    if (t >= 4096) return;
    int a = t >> 6, b = t & 63;
    int y = 2 * a + PAD, x = 2 * b + PAD;
    float s = 0.f;
    #pragma unroll
    for (int i = 0; i < KSZ; i++) {
        int ry = y - i;
        if ((unsigned)ry >= (unsigned)L1) continue;
        int rowbase = ry * L1;
        #pragma unroll
        for (int j = 0; j < KSZ; j++) {
            int rx = x - j;
            if ((unsigned)rx >= (unsigned)L1) continue;
            s += mem[g_idx[rowbase + rx] * KDIM + i * KSZ + j];
        }
    }
    g_raw[t] = s;
}

// max-normalize (single block)
__global__ void normalize_out(float* __restrict__ out) {
    __shared__ float smx[256];
    int tid = threadIdx.x;
    float mx = -3.4e38f;
    for (int i = tid; i < 4096; i += 256) mx = fmaxf(mx, g_raw[i]);
    smx[tid] = mx;
    __syncthreads();
    for (int o = 128; o; o >>= 1) {
        if (tid < o) smx[tid] = fmaxf(smx[tid], smx[tid + o]);
        __syncthreads();
    }
    float m = smx[0];
    for (int i = tid; i < 4096; i += 256) out[i] = g_raw[i] / m;
}

// ---------------------------------------------------------------------------
extern "C" void kernel_launch(void* const* d_in, const int* in_sizes, int n_in,
                              void* d_out, int out_size) {
    const float* image = (const float*)d_in[0];   // 64*64
    const float* mem   = (const float*)d_in[1];   // 16384*225
    float* out = (float*)d_out;                   // 64*64

    cudaFuncSetAttribute(gemm_argmin,
                         cudaFuncAttributeMaxDynamicSharedMemorySize,
                         GEMM_SMEM);

    {
        int n = 4 * BPC * 64 * 32;
        prep_Ah<<<(n + 255) / 256, 256>>>(image);
    }
    {
        int n = 4 * NMEM * 32;
        prep_Bh<<<(n + 255) / 256, 256>>>(mem);
    }
    prep_norms<<<(NMEM * 32) / 256, 256>>>(mem);

    gemm_argmin<<<GEMM_BLOCKS, GEMM_THREADS, GEMM_SMEM>>>();

    repair<<<(MQ + 255) / 256, 256>>>(image);
    recon<<<16, 256>>>(mem);
    normalize_out<<<1, 256>>>(out);
}